// round 4
// baseline (speedup 1.0000x reference)
#include <cuda_runtime.h>
#include <cstdint>

#define MAXN   1024
#define WIDTH  256
#define HEIGHT 256
#define EPS2D  0.3f
#define LOG2E  1.4426950408889634f
#define NTILE  32              // 32x32 tiles of 8x8 px
#define NSEG   8

// device-global scratch (allocation rules: no cudaMalloc)
__device__ float4   dtA[MAXN], dtB[MAXN], dtBox[MAXN];
__device__ float4   dgA[MAXN], dgB[MAXN];
__device__ unsigned dmask[NTILE*NTILE*32];   // 1024-bit mask per tile, 128KB

__device__ __forceinline__ float fast_ex2(float x) {
    float y; asm("ex2.approx.f32 %0, %1;" : "=f"(y) : "f"(x)); return y;
}
__device__ __forceinline__ float sigmoidf(float x) { return 1.f / (1.f + expf(-x)); }

// bin one gaussian (sorted position i, bbox bb) into the tile masks
__device__ __forceinline__ void bin_box(float4 bb, int i) {
    if (bb.x > bb.y) return;                       // degenerate (culled)
    int txlo = max(0, (int)floorf((bb.x - 7.5f) * 0.125f));
    int txhi = min(NTILE-1, (int)ceilf ((bb.y - 0.5f) * 0.125f));
    int tylo = max(0, (int)floorf((bb.z - 7.5f) * 0.125f));
    int tyhi = min(NTILE-1, (int)ceilf ((bb.w - 0.5f) * 0.125f));
    unsigned word = (unsigned)i >> 5;
    unsigned bit  = 1u << (i & 31);
    for (int ty = tylo; ty <= tyhi; ty++) {
        float y0 = ty*8 + 0.5f, y1 = ty*8 + 7.5f;
        if (bb.z > y1 || bb.w < y0) continue;
        for (int tx = txlo; tx <= txhi; tx++) {
            float x0 = tx*8 + 0.5f, x1 = tx*8 + 7.5f;
            if (bb.x > x1 || bb.y < x0) continue;
            atomicOr(&dmask[(ty*NTILE + tx)*32 + word], bit);
        }
    }
}

// ---------------------------------------------------------------------------
// Kernel 1: preprocess + depth sort + tile binning (single block, 1024 thr).
// Fast path: all view-space z identical -> stable sort == identity.
// ---------------------------------------------------------------------------
__global__ __launch_bounds__(1024)
void prep_kernel(const float* __restrict__ means,
                 const float* __restrict__ quats,
                 const float* __restrict__ scales,
                 const float* __restrict__ opac,
                 const float* __restrict__ rgbs,
                 const float* __restrict__ vm,
                 const float* __restrict__ Km,
                 int n)
{
    __shared__ float s_pz0;
    __shared__ unsigned long long skey[MAXN];
    int i = threadIdx.x;

    // zero tile masks (1024 thr x 32 words = 32768 words)
    #pragma unroll
    for (int w = 0; w < 32; w++) dmask[i*32 + w] = 0u;

    float4 Aval, Bval, Boxval;
    float pz = 0.f;

    if (i < n) {
        float R00=vm[0],R01=vm[1],R02=vm[2],t0=vm[3];
        float R10=vm[4],R11=vm[5],R12=vm[6],t1=vm[7];
        float R20=vm[8],R21=vm[9],R22=vm[10],t2=vm[11];
        float mx=means[3*i], my=means[3*i+1], mz=means[3*i+2];
        float px = R00*mx + R01*my + R02*mz + t0;
        float py = R10*mx + R11*my + R12*mz + t1;
        pz       = R20*mx + R21*my + R22*mz + t2;
        float fx=Km[0], cx=Km[2], fy=Km[4], cy=Km[5];
        float iz = 1.f / pz;
        float u = fx*px*iz + cx;
        float v = fy*py*iz + cy;

        float qw=quats[4*i], qx=quats[4*i+1], qy=quats[4*i+2], qz=quats[4*i+3];
        float qin = 1.f / (sqrtf(qw*qw + qx*qx + qy*qy + qz*qz) + 1e-8f);
        qw*=qin; qx*=qin; qy*=qin; qz*=qin;
        float Rq[3][3];
        Rq[0][0]=1.f-2.f*(qy*qy+qz*qz); Rq[0][1]=2.f*(qx*qy-qw*qz); Rq[0][2]=2.f*(qx*qz+qw*qy);
        Rq[1][0]=2.f*(qx*qy+qw*qz); Rq[1][1]=1.f-2.f*(qx*qx+qz*qz); Rq[1][2]=2.f*(qy*qz-qw*qx);
        Rq[2][0]=2.f*(qx*qz-qw*qy); Rq[2][1]=2.f*(qy*qz+qw*qx); Rq[2][2]=1.f-2.f*(qx*qx+qy*qy);

        float s0=scales[3*i], s1=scales[3*i+1], s2=scales[3*i+2];
        float ss0=s0*s0, ss1=s1*s1, ss2=s2*s2;

        float S3[3][3];
        #pragma unroll
        for (int r=0;r<3;r++)
            #pragma unroll
            for (int c=0;c<3;c++)
                S3[r][c] = Rq[r][0]*Rq[c][0]*ss0 + Rq[r][1]*Rq[c][1]*ss1 + Rq[r][2]*Rq[c][2]*ss2;

        float Rv[3][3] = {{R00,R01,R02},{R10,R11,R12},{R20,R21,R22}};
        float tm[3][3], Sc[3][3];
        #pragma unroll
        for (int r=0;r<3;r++)
            #pragma unroll
            for (int c=0;c<3;c++)
                tm[r][c] = Rv[r][0]*S3[0][c] + Rv[r][1]*S3[1][c] + Rv[r][2]*S3[2][c];
        #pragma unroll
        for (int r=0;r<3;r++)
            #pragma unroll
            for (int c=0;c<3;c++)
                Sc[r][c] = tm[r][0]*Rv[c][0] + tm[r][1]*Rv[c][1] + tm[r][2]*Rv[c][2];

        float j00 = fx*iz,          j02 = -fx*px*iz*iz;
        float j11 = fy*iz,          j12 = -fy*py*iz*iz;
        float w0x = Sc[0][0]*j00 + Sc[0][2]*j02;
        float w0z = Sc[2][0]*j00 + Sc[2][2]*j02;
        float w1x = Sc[0][1]*j11 + Sc[0][2]*j12;
        float w1y = Sc[1][1]*j11 + Sc[1][2]*j12;
        float w1z = Sc[2][1]*j11 + Sc[2][2]*j12;

        float a = j00*w0x + j02*w0z + EPS2D;
        float b = j00*w1x + j02*w1z;
        float c = j11*w1y + j12*w1z + EPS2D;

        float det = a*c - b*b;
        float idet = 1.f / det;
        float ia =  c*idet;
        float ib = -b*idet;
        float ic =  a*idet;

        float op  = sigmoidf(opac[i]);
        float col = sigmoidf(rgbs[i]);

        float tau = logf(255.f * op);
        if (tau > 0.f) {
            float rx = sqrtf(2.f*tau*a) + 1e-3f;
            float ry = sqrtf(2.f*tau*c) + 1e-3f;
            Boxval = make_float4(u - rx, u + rx, v - ry, v + ry);
        } else {
            Boxval = make_float4(1e9f, -1e9f, 1e9f, -1e9f);
        }

        Aval = make_float4(u, v, 0.5f*LOG2E*ia, LOG2E*ib);
        Bval = make_float4(0.5f*LOG2E*ic, op, col, 0.f);
    }

    if (i == 0) s_pz0 = pz;
    __syncthreads();   // also orders the mask zeroing before all binning below
    bool same = (i >= n) || (pz == s_pz0);
    if (__syncthreads_and(same)) {
        // stable sort of identical keys == identity permutation
        if (i < n) {
            dgA[i] = Aval; dgB[i] = Bval;
            bin_box(Boxval, i);
        }
        return;
    }

    // general path: bitonic sort on (z, idx)
    unsigned long long key = 0xFFFFFFFFFFFFFFFFULL;
    if (i < n) {
        dtA[i] = Aval; dtB[i] = Bval; dtBox[i] = Boxval;
        unsigned ub = __float_as_uint(pz);
        ub = (ub & 0x80000000u) ? ~ub : (ub | 0x80000000u);
        key = ((unsigned long long)ub << 32) | (unsigned)i;
    }
    skey[i] = key;
    __syncthreads();

    for (unsigned k = 2; k <= MAXN; k <<= 1) {
        for (unsigned j = k >> 1; j > 0; j >>= 1) {
            unsigned ixj = (unsigned)i ^ j;
            if (ixj > (unsigned)i) {
                unsigned long long A = skey[i], B = skey[ixj];
                bool up = ((i & k) == 0);
                if ((A > B) == up) { skey[i] = B; skey[ixj] = A; }
            }
            __syncthreads();
        }
    }

    unsigned long long kk = skey[i];
    if (i < n) {
        int src = (int)(kk & 0xFFFFFFFFu);
        dgA[i] = dtA[src];
        dgB[i] = dtB[src];
        bin_box(dtBox[src], i);
    }
}

// ---------------------------------------------------------------------------
// Kernel 2: 8x8-px tiles, 1024 blocks x 512 threads = 64 px x 8 segments.
// Reads the tile's 1024-bit depth-ordered mask; cold tiles exit immediately;
// hot tiles do parallel rank-select compaction into shared, then segmented
// front-to-back compositing combined via over-operator associativity.
// ---------------------------------------------------------------------------
__global__ __launch_bounds__(512)
void render_kernel(float* __restrict__ out, int n)
{
    __shared__ unsigned smask[32];
    __shared__ int      sPfx[33];        // exclusive prefix of per-word popc
    __shared__ float4   sA[MAXN];
    __shared__ float4   sB[MAXN];
    __shared__ float    segC[NSEG][64];
    __shared__ float    segT[NSEG][64];

    int tid = threadIdx.x;
    int seg = tid >> 6;                  // 0..7
    int pix = tid & 63;                  // 0..63
    int tx  = blockIdx.x & (NTILE-1);
    int ty  = blockIdx.x >> 5;
    int x   = tx*8 + (pix & 7);
    int y   = ty*8 + (pix >> 3);
    float pxc = x + 0.5f, pyc = y + 0.5f;

    if (tid < 32) {
        unsigned m = dmask[blockIdx.x*32 + tid];
        smask[tid] = m;
        int c = __popc(m);
        int incl = c;
        #pragma unroll
        for (int s = 1; s < 32; s <<= 1) {
            int up = __shfl_up_sync(0xFFFFFFFFu, incl, s);
            if (tid >= s) incl += up;
        }
        sPfx[tid] = incl - c;
        if (tid == 31) sPfx[32] = incl;
    }
    __syncthreads();

    int total = sPfx[32];
    if (total == 0) {
        if (seg == 0) out[y*WIDTH + x] = 0.f;
        return;
    }

    // parallel rank-select compaction: list position t -> gaussian index
    for (int t = tid; t < total; t += 512) {
        int w = 0;
        #pragma unroll
        for (int s = 16; s > 0; s >>= 1) {
            int m = w + s;
            if (m <= 31 && sPfx[m] <= t) w = m;
        }
        int r = t - sPfx[w];
        unsigned m = smask[w];
        for (int k = 0; k < r; k++) m &= m - 1u;   // clear r lowest set bits
        int gi = w*32 + (__ffs(m) - 1);
        sA[t] = dgA[gi];
        sB[t] = dgB[gi];
    }
    __syncthreads();

    // per-(pixel, segment) front-to-back compositing over contiguous chunk
    int per = (total + NSEG - 1) >> 3;
    int s0  = seg * per;
    int s1  = s0 + per; if (s1 > total) s1 = total;

    float T = 1.f, c = 0.f;
    for (int j = s0; j < s1; j++) {
        float4 A = sA[j];
        float4 B = sB[j];
        float dx = pxc - A.x;
        float dy = pyc - A.y;
        float e = fmaf(A.z*dx, dx, fmaf(B.x*dy, dy, A.w*dx*dy));
        float alpha = B.y * fast_ex2(-e);
        alpha = fminf(alpha, 0.999f);
        if (e >= 0.f && alpha >= (1.0f/255.0f)) {
            c = fmaf(alpha*T, B.z, c);
            T *= (1.f - alpha);
            if (T <= 1e-4f) break;     // tail < 1e-4 absolute
        }
    }
    segC[seg][pix] = c;
    segT[seg][pix] = T;
    __syncthreads();

    // combine the 8 depth-ordered segments
    if (seg == 0) {
        float img = c;
        float Tp  = T;
        #pragma unroll
        for (int s = 1; s < NSEG; s++) {
            img = fmaf(Tp, segC[s][pix], img);
            Tp *= segT[s][pix];
        }
        out[y*WIDTH + x] = img;
    }
}

// ---------------------------------------------------------------------------
extern "C" void kernel_launch(void* const* d_in, const int* in_sizes, int n_in,
                              void* d_out, int out_size)
{
    const float* means   = (const float*)d_in[0];
    const float* quats   = (const float*)d_in[1];
    const float* scales  = (const float*)d_in[2];
    const float* opac    = (const float*)d_in[3];
    const float* rgbs    = (const float*)d_in[4];
    const float* viewmat = (const float*)d_in[5];
    const float* Km      = (const float*)d_in[6];
    int n = in_sizes[3];            // opacities: one per gaussian
    if (n > MAXN) n = MAXN;

    prep_kernel<<<1, 1024>>>(means, quats, scales, opac, rgbs, viewmat, Km, n);
    render_kernel<<<NTILE*NTILE, 512>>>((float*)d_out, n);
}

// round 5
// speedup vs baseline: 1.7478x; 1.7478x over previous
#include <cuda_runtime.h>
#include <cstdint>

#define MAXN   1024
#define WIDTH  256
#define HEIGHT 256
#define EPS2D  0.3f
#define LOG2E  1.4426950408889634f
#define NTILE  32              // 32x32 tiles of 8x8 px
#define NSEG   4

// device-global scratch (allocation rules: no cudaMalloc)
// dmask starts zero (module init) and every render block re-zeroes the words
// it consumed, so "dmask == 0 at prep entry" holds on every call.
__device__ float4   dtA[MAXN], dtB[MAXN], dtBox[MAXN];
__device__ float4   dgA[MAXN], dgB[MAXN];
__device__ unsigned dmask[NTILE*NTILE*32];   // 1024-bit depth-ordered mask per tile

__device__ __forceinline__ float fast_ex2(float x) {
    float y; asm("ex2.approx.f32 %0, %1;" : "=f"(y) : "f"(x)); return y;
}
__device__ __forceinline__ float sigmoidf(float x) { return 1.f / (1.f + expf(-x)); }

// bin one gaussian (sorted position i, bbox bb) into the tile masks
__device__ __forceinline__ void bin_box(float4 bb, int i) {
    if (bb.x > bb.y) return;                       // degenerate (culled)
    int txlo = max(0, (int)floorf((bb.x - 7.5f) * 0.125f));
    int txhi = min(NTILE-1, (int)ceilf ((bb.y - 0.5f) * 0.125f));
    int tylo = max(0, (int)floorf((bb.z - 7.5f) * 0.125f));
    int tyhi = min(NTILE-1, (int)ceilf ((bb.w - 0.5f) * 0.125f));
    unsigned word = (unsigned)i >> 5;
    unsigned bit  = 1u << (i & 31);
    for (int ty = tylo; ty <= tyhi; ty++) {
        float y0 = ty*8 + 0.5f, y1 = ty*8 + 7.5f;
        if (bb.z > y1 || bb.w < y0) continue;
        for (int tx = txlo; tx <= txhi; tx++) {
            float x0 = tx*8 + 0.5f, x1 = tx*8 + 7.5f;
            if (bb.x > x1 || bb.y < x0) continue;
            atomicOr(&dmask[(ty*NTILE + tx)*32 + word], bit);   // REDG.OR, no return
        }
    }
}

// ---------------------------------------------------------------------------
// Kernel 1: preprocess + depth sort + tile binning (single block, 1024 thr).
// Fast path: all view-space z identical -> stable sort == identity.
// ---------------------------------------------------------------------------
__global__ __launch_bounds__(1024)
void prep_kernel(const float* __restrict__ means,
                 const float* __restrict__ quats,
                 const float* __restrict__ scales,
                 const float* __restrict__ opac,
                 const float* __restrict__ rgbs,
                 const float* __restrict__ vm,
                 const float* __restrict__ Km,
                 int n)
{
    __shared__ float s_pz0;
    __shared__ unsigned long long skey[MAXN];
    int i = threadIdx.x;

    float4 Aval, Bval, Boxval;
    float pz = 0.f;

    if (i < n) {
        float R00=vm[0],R01=vm[1],R02=vm[2],t0=vm[3];
        float R10=vm[4],R11=vm[5],R12=vm[6],t1=vm[7];
        float R20=vm[8],R21=vm[9],R22=vm[10],t2=vm[11];
        float mx=means[3*i], my=means[3*i+1], mz=means[3*i+2];
        float px = R00*mx + R01*my + R02*mz + t0;
        float py = R10*mx + R11*my + R12*mz + t1;
        pz       = R20*mx + R21*my + R22*mz + t2;
        float fx=Km[0], cx=Km[2], fy=Km[4], cy=Km[5];
        float iz = 1.f / pz;
        float u = fx*px*iz + cx;
        float v = fy*py*iz + cy;

        float qw=quats[4*i], qx=quats[4*i+1], qy=quats[4*i+2], qz=quats[4*i+3];
        float qin = 1.f / (sqrtf(qw*qw + qx*qx + qy*qy + qz*qz) + 1e-8f);
        qw*=qin; qx*=qin; qy*=qin; qz*=qin;
        float Rq[3][3];
        Rq[0][0]=1.f-2.f*(qy*qy+qz*qz); Rq[0][1]=2.f*(qx*qy-qw*qz); Rq[0][2]=2.f*(qx*qz+qw*qy);
        Rq[1][0]=2.f*(qx*qy+qw*qz); Rq[1][1]=1.f-2.f*(qx*qx+qz*qz); Rq[1][2]=2.f*(qy*qz-qw*qx);
        Rq[2][0]=2.f*(qx*qz-qw*qy); Rq[2][1]=2.f*(qy*qz+qw*qx); Rq[2][2]=1.f-2.f*(qx*qx+qy*qy);

        float s0=scales[3*i], s1=scales[3*i+1], s2=scales[3*i+2];
        float ss0=s0*s0, ss1=s1*s1, ss2=s2*s2;

        float S3[3][3];
        #pragma unroll
        for (int r=0;r<3;r++)
            #pragma unroll
            for (int c=0;c<3;c++)
                S3[r][c] = Rq[r][0]*Rq[c][0]*ss0 + Rq[r][1]*Rq[c][1]*ss1 + Rq[r][2]*Rq[c][2]*ss2;

        float Rv[3][3] = {{R00,R01,R02},{R10,R11,R12},{R20,R21,R22}};
        float tm[3][3], Sc[3][3];
        #pragma unroll
        for (int r=0;r<3;r++)
            #pragma unroll
            for (int c=0;c<3;c++)
                tm[r][c] = Rv[r][0]*S3[0][c] + Rv[r][1]*S3[1][c] + Rv[r][2]*S3[2][c];
        #pragma unroll
        for (int r=0;r<3;r++)
            #pragma unroll
            for (int c=0;c<3;c++)
                Sc[r][c] = tm[r][0]*Rv[c][0] + tm[r][1]*Rv[c][1] + tm[r][2]*Rv[c][2];

        float j00 = fx*iz,          j02 = -fx*px*iz*iz;
        float j11 = fy*iz,          j12 = -fy*py*iz*iz;
        float w0x = Sc[0][0]*j00 + Sc[0][2]*j02;
        float w0z = Sc[2][0]*j00 + Sc[2][2]*j02;
        float w1x = Sc[0][1]*j11 + Sc[0][2]*j12;
        float w1y = Sc[1][1]*j11 + Sc[1][2]*j12;
        float w1z = Sc[2][1]*j11 + Sc[2][2]*j12;

        float a = j00*w0x + j02*w0z + EPS2D;
        float b = j00*w1x + j02*w1z;
        float c = j11*w1y + j12*w1z + EPS2D;

        float det = a*c - b*b;
        float idet = 1.f / det;
        float ia =  c*idet;
        float ib = -b*idet;
        float ic =  a*idet;

        float op  = sigmoidf(opac[i]);
        float col = sigmoidf(rgbs[i]);

        float tau = logf(255.f * op);
        if (tau > 0.f) {
            float rx = sqrtf(2.f*tau*a) + 1e-3f;
            float ry = sqrtf(2.f*tau*c) + 1e-3f;
            Boxval = make_float4(u - rx, u + rx, v - ry, v + ry);
        } else {
            Boxval = make_float4(1e9f, -1e9f, 1e9f, -1e9f);
        }

        Aval = make_float4(u, v, 0.5f*LOG2E*ia, LOG2E*ib);
        Bval = make_float4(0.5f*LOG2E*ic, op, col, 0.f);
    }

    if (i == 0) s_pz0 = pz;
    __syncthreads();
    bool same = (i >= n) || (pz == s_pz0);
    if (__syncthreads_and(same)) {
        // stable sort of identical keys == identity permutation
        if (i < n) {
            dgA[i] = Aval; dgB[i] = Bval;
            bin_box(Boxval, i);
        }
        return;
    }

    // general path: bitonic sort on (z, idx)
    unsigned long long key = 0xFFFFFFFFFFFFFFFFULL;
    if (i < n) {
        dtA[i] = Aval; dtB[i] = Bval; dtBox[i] = Boxval;
        unsigned ub = __float_as_uint(pz);
        ub = (ub & 0x80000000u) ? ~ub : (ub | 0x80000000u);
        key = ((unsigned long long)ub << 32) | (unsigned)i;
    }
    skey[i] = key;
    __syncthreads();

    for (unsigned k = 2; k <= MAXN; k <<= 1) {
        for (unsigned j = k >> 1; j > 0; j >>= 1) {
            unsigned ixj = (unsigned)i ^ j;
            if (ixj > (unsigned)i) {
                unsigned long long A = skey[i], B = skey[ixj];
                bool up = ((i & k) == 0);
                if ((A > B) == up) { skey[i] = B; skey[ixj] = A; }
            }
            __syncthreads();
        }
    }

    unsigned long long kk = skey[i];
    if (i < n) {
        int src = (int)(kk & 0xFFFFFFFFu);
        dgA[i] = dtA[src];
        dgB[i] = dtB[src];
        bin_box(dtBox[src], i);
    }
}

// ---------------------------------------------------------------------------
// Kernel 2: 8x8-px tiles, 1024 blocks x 256 threads = 64 px x 4 segments.
// Reads (and immediately re-zeroes) the tile's 1024-bit depth-ordered mask;
// cold tiles exit after writing zeros; hot tiles do parallel rank-select
// compaction into shared, then segmented front-to-back compositing combined
// via over-operator associativity.
// ---------------------------------------------------------------------------
__global__ __launch_bounds__(256)
void render_kernel(float* __restrict__ out, int n)
{
    __shared__ unsigned smask[32];
    __shared__ int      sPfx[33];        // exclusive prefix of per-word popc
    __shared__ float4   sA[MAXN];
    __shared__ float4   sB[MAXN];
    __shared__ float    segC[NSEG][64];
    __shared__ float    segT[NSEG][64];

    int tid = threadIdx.x;
    int seg = tid >> 6;                  // 0..3
    int pix = tid & 63;                  // 0..63
    int tx  = blockIdx.x & (NTILE-1);
    int ty  = blockIdx.x >> 5;
    int x   = tx*8 + (pix & 7);
    int y   = ty*8 + (pix >> 3);
    float pxc = x + 0.5f, pyc = y + 0.5f;

    if (tid < 32) {
        unsigned m = dmask[blockIdx.x*32 + tid];
        dmask[blockIdx.x*32 + tid] = 0u;     // restore invariant for next call
        smask[tid] = m;
        int c = __popc(m);
        int incl = c;
        #pragma unroll
        for (int s = 1; s < 32; s <<= 1) {
            int up = __shfl_up_sync(0xFFFFFFFFu, incl, s);
            if (tid >= s) incl += up;
        }
        sPfx[tid] = incl - c;
        if (tid == 31) sPfx[32] = incl;
    }
    __syncthreads();

    int total = sPfx[32];
    if (total == 0) {
        if (seg == 0) out[y*WIDTH + x] = 0.f;
        return;
    }

    // parallel rank-select compaction: list position t -> gaussian index
    for (int t = tid; t < total; t += 256) {
        int w = 0;
        #pragma unroll
        for (int s = 16; s > 0; s >>= 1) {
            int m = w + s;
            if (m <= 31 && sPfx[m] <= t) w = m;
        }
        int r = t - sPfx[w];
        unsigned m = smask[w];
        for (int k = 0; k < r; k++) m &= m - 1u;   // clear r lowest set bits
        int gi = w*32 + (__ffs(m) - 1);
        sA[t] = dgA[gi];
        sB[t] = dgB[gi];
    }
    __syncthreads();

    // per-(pixel, segment) front-to-back compositing over contiguous chunk
    int per = (total + NSEG - 1) >> 2;
    int s0  = seg * per;
    int s1  = s0 + per; if (s1 > total) s1 = total;

    float T = 1.f, c = 0.f;
    for (int j = s0; j < s1; j++) {
        float4 A = sA[j];
        float4 B = sB[j];
        float dx = pxc - A.x;
        float dy = pyc - A.y;
        float e = fmaf(A.z*dx, dx, fmaf(B.x*dy, dy, A.w*dx*dy));
        float alpha = B.y * fast_ex2(-e);
        alpha = fminf(alpha, 0.999f);
        if (e >= 0.f && alpha >= (1.0f/255.0f)) {
            c = fmaf(alpha*T, B.z, c);
            T *= (1.f - alpha);
            if (T <= 1e-4f) break;     // tail < 1e-4 absolute
        }
    }
    segC[seg][pix] = c;
    segT[seg][pix] = T;
    __syncthreads();

    // combine the 4 depth-ordered segments
    if (seg == 0) {
        float img = c;
        float Tp  = T;
        #pragma unroll
        for (int s = 1; s < NSEG; s++) {
            img = fmaf(Tp, segC[s][pix], img);
            Tp *= segT[s][pix];
        }
        out[y*WIDTH + x] = img;
    }
}

// ---------------------------------------------------------------------------
extern "C" void kernel_launch(void* const* d_in, const int* in_sizes, int n_in,
                              void* d_out, int out_size)
{
    const float* means   = (const float*)d_in[0];
    const float* quats   = (const float*)d_in[1];
    const float* scales  = (const float*)d_in[2];
    const float* opac    = (const float*)d_in[3];
    const float* rgbs    = (const float*)d_in[4];
    const float* viewmat = (const float*)d_in[5];
    const float* Km      = (const float*)d_in[6];
    int n = in_sizes[3];            // opacities: one per gaussian
    if (n > MAXN) n = MAXN;

    prep_kernel<<<1, 1024>>>(means, quats, scales, opac, rgbs, viewmat, Km, n);
    render_kernel<<<NTILE*NTILE, 256>>>((float*)d_out, n);
}

// round 6
// speedup vs baseline: 2.1299x; 1.2186x over previous
#include <cuda_runtime.h>
#include <cstdint>

#define MAXN   1024
#define WIDTH  256
#define HEIGHT 256
#define EPS2D  0.3f
#define LOG2E  1.4426950408889634f
#define NTILE  32              // 32x32 tiles of 8x8 px
#define NSEG   8

// device-global scratch (allocation rules: no cudaMalloc)
// dmask starts zero (module init) and every render block re-zeroes the words
// it consumed, so "dmask == 0 at prep entry" holds on every call.
__device__ float4   dtA[MAXN], dtB[MAXN], dtBox[MAXN];
__device__ float4   dgA[MAXN], dgB[MAXN];
__device__ unsigned dmask[NTILE*NTILE*32];   // 1024-bit depth-ordered mask per tile

__device__ __forceinline__ float fast_ex2(float x) {
    float y; asm("ex2.approx.f32 %0, %1;" : "=f"(y) : "f"(x)); return y;
}
__device__ __forceinline__ float sigmoidf(float x) { return 1.f / (1.f + expf(-x)); }

// bin one gaussian (sorted position i, bbox bb) into the tile masks
__device__ __forceinline__ void bin_box(float4 bb, int i) {
    if (bb.x > bb.y) return;                       // degenerate (culled)
    int txlo = max(0, (int)floorf((bb.x - 7.5f) * 0.125f));
    int txhi = min(NTILE-1, (int)ceilf ((bb.y - 0.5f) * 0.125f));
    int tylo = max(0, (int)floorf((bb.z - 7.5f) * 0.125f));
    int tyhi = min(NTILE-1, (int)ceilf ((bb.w - 0.5f) * 0.125f));
    unsigned word = (unsigned)i >> 5;
    unsigned bit  = 1u << (i & 31);
    for (int ty = tylo; ty <= tyhi; ty++) {
        float y0 = ty*8 + 0.5f, y1 = ty*8 + 7.5f;
        if (bb.z > y1 || bb.w < y0) continue;
        for (int tx = txlo; tx <= txhi; tx++) {
            float x0 = tx*8 + 0.5f, x1 = tx*8 + 7.5f;
            if (bb.x > x1 || bb.y < x0) continue;
            atomicOr(&dmask[(ty*NTILE + tx)*32 + word], bit);   // REDG.OR, no return
        }
    }
}

// ---------------------------------------------------------------------------
// Kernel 1: preprocess + depth sort + tile binning (single block, 1024 thr).
// Fast path: all view-space z identical -> stable sort == identity.
// ---------------------------------------------------------------------------
__global__ __launch_bounds__(1024)
void prep_kernel(const float* __restrict__ means,
                 const float* __restrict__ quats,
                 const float* __restrict__ scales,
                 const float* __restrict__ opac,
                 const float* __restrict__ rgbs,
                 const float* __restrict__ vm,
                 const float* __restrict__ Km,
                 int n)
{
    __shared__ float s_pz0;
    __shared__ unsigned long long skey[MAXN];
    int i = threadIdx.x;

    float4 Aval, Bval, Boxval;
    float pz = 0.f;

    if (i < n) {
        float R00=vm[0],R01=vm[1],R02=vm[2],t0=vm[3];
        float R10=vm[4],R11=vm[5],R12=vm[6],t1=vm[7];
        float R20=vm[8],R21=vm[9],R22=vm[10],t2=vm[11];
        float mx=means[3*i], my=means[3*i+1], mz=means[3*i+2];
        float px = R00*mx + R01*my + R02*mz + t0;
        float py = R10*mx + R11*my + R12*mz + t1;
        pz       = R20*mx + R21*my + R22*mz + t2;
        float fx=Km[0], cx=Km[2], fy=Km[4], cy=Km[5];
        float iz = 1.f / pz;
        float u = fx*px*iz + cx;
        float v = fy*py*iz + cy;

        float qw=quats[4*i], qx=quats[4*i+1], qy=quats[4*i+2], qz=quats[4*i+3];
        float qin = 1.f / (sqrtf(qw*qw + qx*qx + qy*qy + qz*qz) + 1e-8f);
        qw*=qin; qx*=qin; qy*=qin; qz*=qin;
        float Rq[3][3];
        Rq[0][0]=1.f-2.f*(qy*qy+qz*qz); Rq[0][1]=2.f*(qx*qy-qw*qz); Rq[0][2]=2.f*(qx*qz+qw*qy);
        Rq[1][0]=2.f*(qx*qy+qw*qz); Rq[1][1]=1.f-2.f*(qx*qx+qz*qz); Rq[1][2]=2.f*(qy*qz-qw*qx);
        Rq[2][0]=2.f*(qx*qz-qw*qy); Rq[2][1]=2.f*(qy*qz+qw*qx); Rq[2][2]=1.f-2.f*(qx*qx+qy*qy);

        float s0=scales[3*i], s1=scales[3*i+1], s2=scales[3*i+2];
        float ss0=s0*s0, ss1=s1*s1, ss2=s2*s2;

        float S3[3][3];
        #pragma unroll
        for (int r=0;r<3;r++)
            #pragma unroll
            for (int c=0;c<3;c++)
                S3[r][c] = Rq[r][0]*Rq[c][0]*ss0 + Rq[r][1]*Rq[c][1]*ss1 + Rq[r][2]*Rq[c][2]*ss2;

        float Rv[3][3] = {{R00,R01,R02},{R10,R11,R12},{R20,R21,R22}};
        float tm[3][3], Sc[3][3];
        #pragma unroll
        for (int r=0;r<3;r++)
            #pragma unroll
            for (int c=0;c<3;c++)
                tm[r][c] = Rv[r][0]*S3[0][c] + Rv[r][1]*S3[1][c] + Rv[r][2]*S3[2][c];
        #pragma unroll
        for (int r=0;r<3;r++)
            #pragma unroll
            for (int c=0;c<3;c++)
                Sc[r][c] = tm[r][0]*Rv[c][0] + tm[r][1]*Rv[c][1] + tm[r][2]*Rv[c][2];

        float j00 = fx*iz,          j02 = -fx*px*iz*iz;
        float j11 = fy*iz,          j12 = -fy*py*iz*iz;
        float w0x = Sc[0][0]*j00 + Sc[0][2]*j02;
        float w0z = Sc[2][0]*j00 + Sc[2][2]*j02;
        float w1x = Sc[0][1]*j11 + Sc[0][2]*j12;
        float w1y = Sc[1][1]*j11 + Sc[1][2]*j12;
        float w1z = Sc[2][1]*j11 + Sc[2][2]*j12;

        float a = j00*w0x + j02*w0z + EPS2D;
        float b = j00*w1x + j02*w1z;
        float c = j11*w1y + j12*w1z + EPS2D;

        float det = a*c - b*b;
        float idet = 1.f / det;
        float ia =  c*idet;
        float ib = -b*idet;
        float ic =  a*idet;

        float op  = sigmoidf(opac[i]);
        float col = sigmoidf(rgbs[i]);

        float tau = logf(255.f * op);
        if (tau > 0.f) {
            float rx = sqrtf(2.f*tau*a) + 1e-3f;
            float ry = sqrtf(2.f*tau*c) + 1e-3f;
            Boxval = make_float4(u - rx, u + rx, v - ry, v + ry);
        } else {
            Boxval = make_float4(1e9f, -1e9f, 1e9f, -1e9f);
        }

        Aval = make_float4(u, v, 0.5f*LOG2E*ia, LOG2E*ib);
        Bval = make_float4(0.5f*LOG2E*ic, op, col, 0.f);
    }

    if (i == 0) s_pz0 = pz;
    __syncthreads();
    bool same = (i >= n) || (pz == s_pz0);
    if (__syncthreads_and(same)) {
        // stable sort of identical keys == identity permutation
        if (i < n) {
            dgA[i] = Aval; dgB[i] = Bval;
            bin_box(Boxval, i);
        }
        return;
    }

    // general path: bitonic sort on (z, idx)
    unsigned long long key = 0xFFFFFFFFFFFFFFFFULL;
    if (i < n) {
        dtA[i] = Aval; dtB[i] = Bval; dtBox[i] = Boxval;
        unsigned ub = __float_as_uint(pz);
        ub = (ub & 0x80000000u) ? ~ub : (ub | 0x80000000u);
        key = ((unsigned long long)ub << 32) | (unsigned)i;
    }
    skey[i] = key;
    __syncthreads();

    for (unsigned k = 2; k <= MAXN; k <<= 1) {
        for (unsigned j = k >> 1; j > 0; j >>= 1) {
            unsigned ixj = (unsigned)i ^ j;
            if (ixj > (unsigned)i) {
                unsigned long long A = skey[i], B = skey[ixj];
                bool up = ((i & k) == 0);
                if ((A > B) == up) { skey[i] = B; skey[ixj] = A; }
            }
            __syncthreads();
        }
    }

    unsigned long long kk = skey[i];
    if (i < n) {
        int src = (int)(kk & 0xFFFFFFFFu);
        dgA[i] = dtA[src];
        dgB[i] = dtB[src];
        bin_box(dtBox[src], i);
    }
}

// ---------------------------------------------------------------------------
// Kernel 2: 8x8-px tiles, 1024 blocks x 512 threads = 64 px x 8 segments.
// Reads (and immediately re-zeroes) the tile's 1024-bit depth-ordered mask;
// cold tiles exit after writing zeros; hot tiles do parallel rank-select
// compaction into shared, then segmented branch-free front-to-back
// compositing combined via over-operator associativity.
// ---------------------------------------------------------------------------
__global__ __launch_bounds__(512)
void render_kernel(float* __restrict__ out, int n)
{
    __shared__ unsigned smask[32];
    __shared__ int      sPfx[33];        // exclusive prefix of per-word popc
    __shared__ float4   sA[MAXN];
    __shared__ float4   sB[MAXN];
    __shared__ float    segC[NSEG][64];
    __shared__ float    segT[NSEG][64];

    int tid = threadIdx.x;
    int seg = tid >> 6;                  // 0..7
    int pix = tid & 63;                  // 0..63
    int tx  = blockIdx.x & (NTILE-1);
    int ty  = blockIdx.x >> 5;
    int x   = tx*8 + (pix & 7);
    int y   = ty*8 + (pix >> 3);
    float pxc = x + 0.5f, pyc = y + 0.5f;

    if (tid < 32) {
        unsigned m = dmask[blockIdx.x*32 + tid];
        dmask[blockIdx.x*32 + tid] = 0u;     // restore invariant for next call
        smask[tid] = m;
        int c = __popc(m);
        int incl = c;
        #pragma unroll
        for (int s = 1; s < 32; s <<= 1) {
            int up = __shfl_up_sync(0xFFFFFFFFu, incl, s);
            if (tid >= s) incl += up;
        }
        sPfx[tid] = incl - c;
        if (tid == 31) sPfx[32] = incl;
    }
    __syncthreads();

    int total = sPfx[32];
    if (total == 0) {
        if (seg == 0) out[y*WIDTH + x] = 0.f;
        return;
    }

    // parallel rank-select compaction: list position t -> gaussian index
    for (int t = tid; t < total; t += 512) {
        int w = 0;
        #pragma unroll
        for (int s = 16; s > 0; s >>= 1) {
            int m = w + s;
            if (m <= 31 && sPfx[m] <= t) w = m;
        }
        int r = t - sPfx[w];
        unsigned m = smask[w];
        for (int k = 0; k < r; k++) m &= m - 1u;   // clear r lowest set bits
        int gi = w*32 + (__ffs(m) - 1);
        sA[t] = dgA[gi];
        sB[t] = dgB[gi];
    }
    __syncthreads();

    // per-(pixel, segment) branch-free compositing over contiguous chunk
    int per = (total + NSEG - 1) >> 3;
    int s0  = seg * per;
    int s1  = s0 + per; if (s1 > total) s1 = total;

    float T = 1.f, c = 0.f;
    for (int j = s0; j < s1; j++) {
        float4 A = sA[j];
        float4 B = sB[j];
        float dx = pxc - A.x;
        float dy = pyc - A.y;
        float e = fmaf(A.z*dx, dx, fmaf(B.x*dy, dy, A.w*dx*dy));
        float alpha = fminf(B.y * fast_ex2(-e), 0.999f);
        bool valid = (e >= 0.f) && (alpha >= (1.0f/255.0f));
        alpha = valid ? alpha : 0.f;              // exact no-op when invalid
        c = fmaf(alpha*T, B.z, c);
        T *= (1.f - alpha);
        if (((j - s0) & 3) == 3 && T <= 1e-4f) break;   // tail < 1e-4 absolute
    }
    segC[seg][pix] = c;
    segT[seg][pix] = T;
    __syncthreads();

    // combine the 8 depth-ordered segments
    if (seg == 0) {
        float img = c;
        float Tp  = T;
        #pragma unroll
        for (int s = 1; s < NSEG; s++) {
            img = fmaf(Tp, segC[s][pix], img);
            Tp *= segT[s][pix];
        }
        out[y*WIDTH + x] = img;
    }
}

// ---------------------------------------------------------------------------
extern "C" void kernel_launch(void* const* d_in, const int* in_sizes, int n_in,
                              void* d_out, int out_size)
{
    const float* means   = (const float*)d_in[0];
    const float* quats   = (const float*)d_in[1];
    const float* scales  = (const float*)d_in[2];
    const float* opac    = (const float*)d_in[3];
    const float* rgbs    = (const float*)d_in[4];
    const float* viewmat = (const float*)d_in[5];
    const float* Km      = (const float*)d_in[6];
    int n = in_sizes[3];            // opacities: one per gaussian
    if (n > MAXN) n = MAXN;

    prep_kernel<<<1, 1024>>>(means, quats, scales, opac, rgbs, viewmat, Km, n);
    render_kernel<<<NTILE*NTILE, 512>>>((float*)d_out, n);
}